// round 17
// baseline (speedup 1.0000x reference)
#include <cuda_runtime.h>
#include <cuda_fp16.h>
#include <cstdint>

#define DEV __device__ __forceinline__

// -------------------- problem sizes --------------------
static constexpr int BATCH = 4096;
static constexpr int ORULE = 256;
static constexpr int DIM   = 256;

static constexpr int M_TILE  = 128;                // batch rows per tile
static constexpr int K_CHUNK = 64;                 // K slice per X buffer
static constexpr int KT_PER_TILE = DIM / K_CHUNK;  // 4
static constexpr int THREADS = 512;                // 16 warps, 4 per SMSP
static constexpr int NTILES  = (BATCH / M_TILE) * ORULE;  // 8192, o-major
static constexpr int NSM     = 148;
static constexpr int TILES_PER_CTA = (NTILES + NSM - 1) / NSM;  // 56
static constexpr int GRID    = (NTILES + TILES_PER_CTA - 1) / TILES_PER_CTA;

// -------------------- smem layout --------------------
// rows padded to 72 halves (144B): conflict-free ldmatrix (R9-verified)
static constexpr int ROWB   = 144;
static constexpr int XBUFB  = M_TILE * ROWB;       // 18432: one X chunk buffer
static constexpr int ABUFB  = DIM * ROWB;          // 36864: one A K-chunk
static constexpr int OFF_X  = 0;                   // 4 ring slots (slot==kt) -> 73728
static constexpr int OFF_A  = 4 * XBUFB;           // 73728; 4 chunks -> 221184
static constexpr int OFF_C  = OFF_A + KT_PER_TILE * ABUFB;  // 221184: c_sm[256]
static constexpr int OFF_P  = OFF_C + 1024;                 // 222208: 128x4 floats
static constexpr int SMEM_TOTAL = OFF_P + 2048;             // 224256

// -------------------- scratch (device globals; no allocation) --------------------
__device__ __align__(16) __half g_Af[(size_t)ORULE * DIM * DIM];  // 33.5 MB
__device__ __align__(16) __half g_xf[(size_t)BATCH * DIM];        // 2 MB

// -------------------- PTX helpers (sm_80-era, compile at compute_103) ----------
DEV uint32_t smem_to_u32(const void* p) {
    uint32_t a;
    asm("{ .reg .u64 t; cvta.to.shared.u64 t, %1; cvt.u32.u64 %0, t; }" : "=r"(a) : "l"(p));
    return a;
}

DEV void cp_async16(uint32_t saddr, const void* g) {
    asm volatile("cp.async.cg.shared.global [%0], [%1], 16;" :: "r"(saddr), "l"(g));
}
#define CP_COMMIT() asm volatile("cp.async.commit_group;" ::: "memory")
#define CP_WAIT(n)  asm volatile("cp.async.wait_group %0;" :: "n"(n) : "memory")

// named-barrier sync over one wmi group (4 warps, 128 threads)
#define BAR_GRP(id) asm volatile("bar.sync %0, 128;" :: "r"(id) : "memory")

#define LDMX4(r0, r1, r2, r3, addr) \
    asm volatile("ldmatrix.sync.aligned.m8n8.x4.shared.b16 {%0,%1,%2,%3}, [%4];" \
                 : "=r"(r0), "=r"(r1), "=r"(r2), "=r"(r3) : "r"(addr))

DEV void mma16816(float* d, const uint32_t* a, uint32_t b0, uint32_t b1) {
    asm volatile(
        "mma.sync.aligned.m16n8k16.row.col.f32.f16.f16.f32 "
        "{%0,%1,%2,%3}, {%4,%5,%6,%7}, {%8,%9}, {%0,%1,%2,%3};"
        : "+f"(d[0]), "+f"(d[1]), "+f"(d[2]), "+f"(d[3])
        : "r"(a[0]), "r"(a[1]), "r"(a[2]), "r"(a[3]), "r"(b0), "r"(b1));
}

// ---- fused prepass: grid (37, 256), 256 threads (R14-verified) ----
__global__ void build_all_kernel(const float* __restrict__ x,
                                 const float* __restrict__ scales,
                                 const float* __restrict__ rots) {
    const int o  = blockIdx.y;
    const int bx = blockIdx.x;
    const int t  = threadIdx.x;

    if (bx == 36) {   // ---- x convert: 4096 floats per block ----
        const float* xs = x + (size_t)o * 4096;
        __half* xd = g_xf + (size_t)o * 4096;
        #pragma unroll
        for (int it = 0; it < 4; it++) {
            int idx = it * 1024 + t * 4;
            float4 v = *reinterpret_cast<const float4*>(xs + idx);
            __half2 h0 = __floats2half2_rn(v.x, v.y);
            __half2 h1 = __floats2half2_rn(v.z, v.w);
            *reinterpret_cast<__half2*>(xd + idx)     = h0;
            *reinterpret_cast<__half2*>(xd + idx + 2) = h1;
        }
        return;
    }

    __shared__ float Us[32][33];
    int tt = bx, bi = 0;
    while (tt >= 8 - bi) { tt -= 8 - bi; bi++; }
    const int bj = bi + tt;
    const size_t base = (size_t)o * DIM * DIM;

    {   // load 32x32 tile of rots (upper source), 4 floats per thread
        int r = t >> 3, c4 = (t & 7) * 4;
        float4 v = *reinterpret_cast<const float4*>(
            rots + base + (size_t)(bi * 32 + r) * DIM + bj * 32 + c4);
        Us[r][c4] = v.x; Us[r][c4 + 1] = v.y; Us[r][c4 + 2] = v.z; Us[r][c4 + 3] = v.w;
    }
    __syncthreads();

    if (t < 128) {   // upper tile: A[bi*32+r][bj*32+c] (diag handling if bi==bj)
        int r = t >> 2, c8 = (t & 3) * 8;
        __half hv[8];
        if (bi == bj) {
            float sc = scales[o * DIM + bi * 32 + r];
            #pragma unroll
            for (int cc = 0; cc < 8; cc++) {
                int c = c8 + cc;
                float val = (c == r) ? sc : (c > r ? Us[r][c] : Us[c][r]);
                hv[cc] = __float2half(val);
            }
        } else {
            #pragma unroll
            for (int cc = 0; cc < 8; cc++) hv[cc] = __float2half(Us[r][c8 + cc]);
        }
        *reinterpret_cast<uint4*>(g_Af + base + (size_t)(bi * 32 + r) * DIM
                                  + bj * 32 + c8) = *reinterpret_cast<uint4*>(hv);
    } else if (bi != bj) {   // mirror tile: A[bj*32+r][bi*32+c] = Us[c][r]
        int t2 = t - 128;
        int r = t2 >> 2, c8 = (t2 & 3) * 8;
        __half hv[8];
        #pragma unroll
        for (int cc = 0; cc < 8; cc++) hv[cc] = __float2half(Us[c8 + cc][r]);
        *reinterpret_cast<uint4*>(g_Af + base + (size_t)(bj * 32 + r) * DIM
                                  + bi * 32 + c8) = *reinterpret_cast<uint4*>(hv);
    }
}

// -------------------- loaders --------------------
// per-GROUP X pair: group wmi loads its 32-row slice of chunks kt0, kt0+1 of 'tile'
// into ring slots kt0, kt0+1 (slot == kt since pairs are tile-aligned)
DEV void issue_x_pair2(uint32_t sb, int wmi, int tig, int tile, int kt0) {
    const int mi = tile & 31;
    #pragma unroll
    for (int j = 0; j < 2; j++) {
        const int kt = kt0 + j;
        const __half* Xb = g_xf + (((size_t)(mi * M_TILE + 32 * wmi)) << 8)
                         + kt * K_CHUNK;
        const uint32_t base = sb + OFF_X + kt * XBUFB + (32 * wmi) * ROWB;
        #pragma unroll
        for (int i = tig; i < 256; i += 128) {      // 32 rows x 8 segs of 16B
            int row = i >> 3, seg = i & 7;
            cp_async16(base + row * ROWB + seg * 16,
                       Xb + ((size_t)row << 8) + seg * 8);
        }
    }
}

// full A[o]: cooperative (all 512 threads), 4 K-chunks, 256 rows x 64 halves each
DEV void issue_A(uint32_t sb, int tid, int o) {
    const __half* Ao = g_Af + ((size_t)o << 16);
    #pragma unroll
    for (int kt = 0; kt < KT_PER_TILE; kt++) {
        const uint32_t base = sb + OFF_A + kt * ABUFB;
        const __half* Ab = Ao + kt * K_CHUNK;
        for (int i = tid; i < 2048; i += THREADS) {
            int row = i >> 3, seg = i & 7;
            cp_async16(base + row * ROWB + seg * 16,
                       Ab + ((size_t)row << 8) + seg * 8);
        }
    }
}

// load one kk's B-operand fragment set (4x LDMX4 from resident A region)
DEV void load_bf_set(uint32_t* bf, uint32_t abase, int wn, int mg, int rr, int kk) {
    #pragma unroll
    for (int nt = 0; nt < 4; nt++) {
        uint32_t addr = abase + (64 * wn + 16 * nt + ((mg >> 1) << 3) + rr) * ROWB
                      + kk * 32 + (mg & 1) * 16;
        LDMX4(bf[nt * 4 + 0], bf[nt * 4 + 1], bf[nt * 4 + 2], bf[nt * 4 + 3], addr);
    }
}

// -------------------- main kernel: persistent, staggered group schedules -----------
__global__ void __launch_bounds__(THREADS, 1)
fuzzy_bell_kernel(const float* __restrict__ centroids,
                  const float* __restrict__ bvec,
                  float* __restrict__ out) {
    extern __shared__ char smem[];
    const uint32_t sb = smem_to_u32(smem);
    const int tid = threadIdx.x;
    const int wid = tid >> 5;
    const int l   = tid & 31;

    const int t_start = blockIdx.x * TILES_PER_CTA;
    if (t_start >= NTILES) return;
    const int t_end = min(t_start + TILES_PER_CTA, NTILES);

    const int wmi  = wid >> 2;   // 0..3: M group (32 rows) — barrier domain
    const int wn   = wid & 3;    // 0..3: N quarter (64 cols)
    const int tig  = tid & 127;  // thread index within group
    const int barid = wmi + 1;   // named barrier id 1..4
    const int mg  = l >> 3, rr = l & 7;

    float* c_sm = reinterpret_cast<float*>(smem + OFF_C);   // [256]
    float* part = reinterpret_cast<float*>(smem + OFF_P);   // [128][4]

    int run0 = t_start;
    while (run0 < t_end) {
        const int o       = run0 >> 5;
        const int gend    = min(t_end, (o + 1) << 5);   // end of this o-run
        const int run_len = gend - run0;
        const int nchunks = run_len * KT_PER_TILE;
        const float bb = __ldg(bvec + o);

        // group-staggered schedule: group wmi starts 'off' tiles into the run
        const int off = (wmi * run_len) >> 2;           // < run_len

        // ---- o-boundary: drain, full sync, load A[o] + centroid + first X pair ----
        CP_WAIT(0);
        __syncthreads();            // all groups done reading previous A/X
        if (tid < 256) c_sm[tid] = centroids[o * DIM + tid];
        issue_A(sb, tid, o);
        CP_COMMIT();                                   // group [A]
        issue_x_pair2(sb, wmi, tig, run0 + off, 0);
        CP_COMMIT();                                   // group [X kt0,kt1 of 1st tile]

        for (int it = 0; it < run_len; it++) {
            int tv = it + off; if (tv >= run_len) tv -= run_len;
            const int tile = run0 + tv;
            const int m0 = (tile & 31) * M_TILE;

            float d[2][8][4];
            #pragma unroll
            for (int a = 0; a < 2; a++)
                #pragma unroll
                for (int bq = 0; bq < 8; bq++)
                    #pragma unroll
                    for (int cq = 0; cq < 4; cq++) d[a][bq][cq] = 0.0f;

            #pragma unroll
            for (int kt = 0; kt < KT_PER_TILE; kt++) {
                const int cg = it * KT_PER_TILE + kt;   // group-local chunk index
                const uint32_t abase = sb + OFF_A + kt * ABUFB;

                uint32_t bf0[16];           // kk=0 B-fragments
                bool preloaded = false;

                if ((kt & 1) == 0) {        // pair boundary: wait + barrier
                    if (cg > 0) {           // A resident & synced -> safe pre-barrier
                        load_bf_set(bf0, abase, wn, mg, rr, 0);
                        preloaded = true;
                    }
                    CP_WAIT(0);             // completes pair covering chunks cg,cg+1
                    if (cg == 0) { __syncthreads(); } else { BAR_GRP(barid); }
                    if (cg + 2 < nchunks) { // prefetch next pair in group order
                        int it2 = (cg + 2) >> 2;
                        int tv2 = it2 + off; if (tv2 >= run_len) tv2 -= run_len;
                        issue_x_pair2(sb, wmi, tig, run0 + tv2, (cg + 2) & 3);
                        CP_COMMIT();
                    }
                }
                if (!preloaded) load_bf_set(bf0, abase, wn, mg, rr, 0);

                const uint32_t xbase = sb + OFF_X + kt * XBUFB;   // slot == kt

                #pragma unroll
                for (int kk = 0; kk < K_CHUNK / 16; kk++) {
                    uint32_t xf[2][4];
                    uint32_t bfl[16];
                    const uint32_t* bfu;
                    if (kk == 0) {
                        bfu = bf0;
                    } else {
                        load_bf_set(bfl, abase, wn, mg, rr, kk);
                        bfu = bfl;
                    }
                    #pragma unroll
                    for (int mt = 0; mt < 2; mt++) {   // X (A-operand) m16k16 frags
                        uint32_t addr = xbase
                                      + (32 * wmi + 16 * mt + (l & 15)) * ROWB
                                      + kk * 32 + (l >> 4) * 16;
                        LDMX4(xf[mt][0], xf[mt][1], xf[mt][2], xf[mt][3], addr);
                    }
                    #pragma unroll
                    for (int mt = 0; mt < 2; mt++)
                        #pragma unroll
                        for (int n8 = 0; n8 < 8; n8++)
                            mma16816(d[mt][n8], xf[mt],
                                     bfu[(n8 >> 1) * 4 + (n8 & 1) * 2],
                                     bfu[(n8 >> 1) * 4 + (n8 & 1) * 2 + 1]);
                }
            }

            // ---- epilogue (group-local): y += centroid, norm, bell membership ----
            #pragma unroll
            for (int mt = 0; mt < 2; mt++) {
                #pragma unroll
                for (int h = 0; h < 2; h++) {
                    float s = 0.0f;
                    #pragma unroll
                    for (int n8 = 0; n8 < 8; n8++) {
                        int n = 64 * wn + 8 * n8 + ((l & 3) << 1);
                        float v0 = d[mt][n8][h * 2]     + c_sm[n];
                        float v1 = d[mt][n8][h * 2 + 1] + c_sm[n + 1];
                        s = fmaf(v0, v0, fmaf(v1, v1, s));
                    }
                    s += __shfl_xor_sync(0xffffffffu, s, 1);
                    s += __shfl_xor_sync(0xffffffffu, s, 2);
                    if ((l & 3) == 0)
                        part[(32 * wmi + 16 * mt + 8 * h + (l >> 2)) * 4 + wn] = s;
                }
            }
            BAR_GRP(barid);   // publish part within group

            if (wn == 0) {    // group's first warp finalizes its 32 rows
                int r = 32 * wmi + l;
                float acc = part[r * 4] + part[r * 4 + 1]
                          + part[r * 4 + 2] + part[r * 4 + 3];
                float p = exp2f(bb * log2f(acc));   // (rx^2)^b = rx^(2b)
                out[(size_t)(m0 + r) * ORULE + o] = 1.0f / (1.0f + p);
            }
            // part rows are group-private; reuse ordered by this group's barriers
        }
        run0 = gend;
    }
}

// -------------------- launch --------------------
extern "C" void kernel_launch(void* const* d_in, const int* in_sizes, int n_in,
                              void* d_out, int out_size) {
    (void)in_sizes; (void)n_in; (void)out_size;
    const float* x         = (const float*)d_in[0];   // [4096,256]
    const float* scales    = (const float*)d_in[1];   // [256,256]
    const float* rots      = (const float*)d_in[2];   // [256,256,256]
    const float* centroids = (const float*)d_in[3];   // [256,256,1]
    const float* bvec      = (const float*)d_in[4];   // [256]
    float* out = (float*)d_out;                       // [4096,256]

    cudaFuncSetAttribute(fuzzy_bell_kernel,
                         cudaFuncAttributeMaxDynamicSharedMemorySize, SMEM_TOTAL);

    build_all_kernel<<<dim3(37, ORULE), 256>>>(x, scales, rots);
    fuzzy_bell_kernel<<<GRID, THREADS, SMEM_TOTAL>>>(centroids, bvec, out);
}